// round 1
// baseline (speedup 1.0000x reference)
#include <cuda_runtime.h>
#include <math.h>

#define BB 8
#define NN 8192
#define SS 2048
#define C1 128
#define C2 256
#define CIN 384
#define H1 256
#define H2 128
#define M_TOTAL (BB * NN)   /* 65536 */
#define BN_EPS 1e-5f

// ---------------- scratch (static device globals; no allocation) ----------------
__device__ float g_interp[(size_t)M_TOTAL * C2];   // 64 MB: interpolated features
__device__ float g_y[(size_t)M_TOTAL * H1];        // 64 MB: GEMM1 output (pre-BN)
__device__ float g_sum1[H1];
__device__ float g_sumsq1[H1];
__device__ float g_sum2[H2];
__device__ float g_sumsq2[H2];
__device__ float g_scale1[H1];
__device__ float g_shift1[H1];
__device__ float g_scale2[H2];
__device__ float g_shift2[H2];

// ---------------- kernel 0: zero stats accumulators ----------------
__global__ void zero_stats_kernel() {
    int t = threadIdx.x;
    if (t < H1) { g_sum1[t] = 0.f; g_sumsq1[t] = 0.f; }
    if (t < H2) { g_sum2[t] = 0.f; g_sumsq2[t] = 0.f; }
}

// ---------------- kernel 1: 3-NN + inverse-distance interpolation ----------------
// grid: (N/256, B), block: 256 threads. One query point per thread for KNN,
// then warp-cooperative gather of the 3 neighbor feature rows (coalesced).
__global__ __launch_bounds__(256) void knn_interp_kernel(
    const float* __restrict__ xyz1,
    const float* __restrict__ xyz2,
    const float* __restrict__ feat2)
{
    __shared__ float4 s_p[SS];      // (x, y, z, |p|^2) for all 2048 candidates: 32 KB
    __shared__ float  s_w[256][3];
    __shared__ int    s_i[256][3];

    const int b   = blockIdx.y;
    const int n0  = blockIdx.x * 256;
    const int tid = threadIdx.x;

    // stage xyz2 for this batch into smem, with precomputed squared norm
    const float* p2 = xyz2 + (size_t)b * SS * 3;
    for (int j = tid; j < SS; j += 256) {
        float x = p2[j * 3 + 0];
        float y = p2[j * 3 + 1];
        float z = p2[j * 3 + 2];
        s_p[j] = make_float4(x, y, z, x * x + y * y + z * z);
    }
    __syncthreads();

    // ---- per-thread 3-NN over 2048 candidates ----
    const int   n   = n0 + tid;
    const float* q  = xyz1 + ((size_t)b * NN + n) * 3;
    const float qx = q[0], qy = q[1], qz = q[2];
    const float n1 = qx * qx + qy * qy + qz * qz;
    const float mx = -2.f * qx, my = -2.f * qy, mz = -2.f * qz;

    // score s = |p|^2 - 2 q.p  (ordering identical to reference's gram-trick d2)
    float d0 = 1e30f, d1 = 1e30f, d2v = 1e30f;
    int   i0 = 0, i1 = 0, i2 = 0;

#pragma unroll 8
    for (int j = 0; j < SS; j++) {
        float4 c = s_p[j];
        float s = fmaf(mx, c.x, fmaf(my, c.y, fmaf(mz, c.z, c.w)));
        if (s < d2v) {
            if (s < d1) {
                d2v = d1; i2 = i1;
                if (s < d0) { d1 = d0; i1 = i0; d0 = s; i0 = j; }
                else        { d1 = s;  i1 = j; }
            } else {
                d2v = s; i2 = j;
            }
        }
    }

    // weights: w = 1/(sqrt(max(n1+s,0)) + 1e-10), normalized
    float da = sqrtf(fmaxf(n1 + d0, 0.f)) + 1e-10f;
    float db = sqrtf(fmaxf(n1 + d1, 0.f)) + 1e-10f;
    float dc = sqrtf(fmaxf(n1 + d2v, 0.f)) + 1e-10f;
    float w0 = 1.f / da, w1 = 1.f / db, w2 = 1.f / dc;
    float inv = 1.f / (w0 + w1 + w2);
    s_w[tid][0] = w0 * inv; s_w[tid][1] = w1 * inv; s_w[tid][2] = w2 * inv;
    s_i[tid][0] = i0; s_i[tid][1] = i1; s_i[tid][2] = i2;
    __syncthreads();

    // ---- warp-cooperative gather: one point at a time per warp, coalesced ----
    const int lane = tid & 31;
    const int warp = tid >> 5;
    const float4* f2b = (const float4*)(feat2 + (size_t)b * SS * C2);
    for (int pl = warp; pl < 256; pl += 8) {
        const float a0 = s_w[pl][0], a1 = s_w[pl][1], a2 = s_w[pl][2];
        const float4* r0 = f2b + (size_t)s_i[pl][0] * (C2 / 4);
        const float4* r1 = f2b + (size_t)s_i[pl][1] * (C2 / 4);
        const float4* r2 = f2b + (size_t)s_i[pl][2] * (C2 / 4);
        float4* dst = (float4*)(g_interp + ((size_t)b * NN + n0 + pl) * C2);
#pragma unroll
        for (int c = lane; c < C2 / 4; c += 32) {
            float4 va = r0[c], vb = r1[c], vc = r2[c];
            float4 o;
            o.x = a0 * va.x + a1 * vb.x + a2 * vc.x;
            o.y = a0 * va.y + a1 * vb.y + a2 * vc.y;
            o.z = a0 * va.z + a1 * vb.z + a2 * vc.z;
            o.w = a0 * va.w + a1 * vb.w + a2 * vc.w;
            dst[c] = o;
        }
    }
}

// ---------------- GEMM tiling parameters ----------------
#define BM 128
#define BNT 128
#define BK 16

// ---------------- kernel 2: GEMM1 + bias + channel stats ----------------
// y[r, o] = sum_k x[r, k] * W1[o, k] + b1[o]
// x = [interp (k<256) | feat1 (k>=256)], read from two sources.
__global__ __launch_bounds__(256) void gemm1_kernel(
    const float* __restrict__ feat1,
    const float* __restrict__ W1,
    const float* __restrict__ b1)
{
    __shared__ float As[BK][BM + 4];
    __shared__ float Bs[BK][BNT + 4];
    __shared__ float s_sum[BNT];
    __shared__ float s_sq[BNT];

    const int tid  = threadIdx.x;
    const int row0 = blockIdx.x * BM;
    const int col0 = blockIdx.y * BNT;
    const int tx = tid & 15;       // output col group
    const int ty = tid >> 4;       // output row group

    if (tid < BNT) { s_sum[tid] = 0.f; s_sq[tid] = 0.f; }

    const int la_r = tid >> 2;           // 0..63
    const int la_k = (tid & 3) * 4;      // 0,4,8,12

    float acc[8][8];
#pragma unroll
    for (int i = 0; i < 8; i++)
#pragma unroll
        for (int j = 0; j < 8; j++) acc[i][j] = 0.f;

    for (int k0 = 0; k0 < CIN; k0 += BK) {
        const float* src; int ld, kk0;
        if (k0 < C2) { src = g_interp; ld = C2; kk0 = k0; }
        else         { src = feat1;    ld = C1; kk0 = k0 - C2; }
#pragma unroll
        for (int h = 0; h < 2; h++) {
            int r = la_r + h * 64;
            float4 v = *(const float4*)(src + (size_t)(row0 + r) * ld + kk0 + la_k);
            As[la_k + 0][r] = v.x; As[la_k + 1][r] = v.y;
            As[la_k + 2][r] = v.z; As[la_k + 3][r] = v.w;
        }
#pragma unroll
        for (int h = 0; h < 2; h++) {
            int c = la_r + h * 64;
            float4 v = *(const float4*)(W1 + (size_t)(col0 + c) * CIN + k0 + la_k);
            Bs[la_k + 0][c] = v.x; Bs[la_k + 1][c] = v.y;
            Bs[la_k + 2][c] = v.z; Bs[la_k + 3][c] = v.w;
        }
        __syncthreads();
#pragma unroll
        for (int kk = 0; kk < BK; kk++) {
            float a[8], bv[8];
            *(float4*)&a[0]  = *(const float4*)&As[kk][ty * 8];
            *(float4*)&a[4]  = *(const float4*)&As[kk][ty * 8 + 4];
            *(float4*)&bv[0] = *(const float4*)&Bs[kk][tx * 8];
            *(float4*)&bv[4] = *(const float4*)&Bs[kk][tx * 8 + 4];
#pragma unroll
            for (int i = 0; i < 8; i++)
#pragma unroll
                for (int j = 0; j < 8; j++)
                    acc[i][j] = fmaf(a[i], bv[j], acc[i][j]);
        }
        __syncthreads();
    }

    // epilogue: +bias, store y, accumulate per-channel sum/sumsq
    float bias[8];
#pragma unroll
    for (int j = 0; j < 8; j++) bias[j] = b1[col0 + tx * 8 + j];

    float cs[8], cq[8];
#pragma unroll
    for (int j = 0; j < 8; j++) { cs[j] = 0.f; cq[j] = 0.f; }

#pragma unroll
    for (int i = 0; i < 8; i++) {
        const int r = row0 + ty * 8 + i;
        float* yr = g_y + (size_t)r * H1 + col0 + tx * 8;
        float v[8];
#pragma unroll
        for (int j = 0; j < 8; j++) {
            v[j] = acc[i][j] + bias[j];
            cs[j] += v[j];
            cq[j] += v[j] * v[j];
        }
        *(float4*)&yr[0] = make_float4(v[0], v[1], v[2], v[3]);
        *(float4*)&yr[4] = make_float4(v[4], v[5], v[6], v[7]);
    }
#pragma unroll
    for (int j = 0; j < 8; j++) {
        atomicAdd(&s_sum[tx * 8 + j], cs[j]);
        atomicAdd(&s_sq[tx * 8 + j], cq[j]);
    }
    __syncthreads();
    if (tid < BNT) {
        atomicAdd(&g_sum1[col0 + tid], s_sum[tid]);
        atomicAdd(&g_sumsq1[col0 + tid], s_sq[tid]);
    }
}

// ---------------- kernel 3: BN1 finalize ----------------
__global__ void bn1_finalize_kernel(const float* __restrict__ g1,
                                    const float* __restrict__ be1)
{
    int c = threadIdx.x;
    if (c < H1) {
        float mean = g_sum1[c] * (1.f / (float)M_TOTAL);
        float var  = g_sumsq1[c] * (1.f / (float)M_TOTAL) - mean * mean;
        float sc   = g1[c] / sqrtf(var + BN_EPS);
        g_scale1[c] = sc;
        g_shift1[c] = be1[c] - mean * sc;
    }
}

// ---------------- kernel 4: GEMM2 (BN1+ReLU fused into A load) + bias + stats ----------------
__global__ __launch_bounds__(256) void gemm2_kernel(
    const float* __restrict__ W2,
    const float* __restrict__ b2,
    float* __restrict__ out)
{
    __shared__ float As[BK][BM + 4];
    __shared__ float Bs[BK][BNT + 4];
    __shared__ float s_sum[BNT];
    __shared__ float s_sq[BNT];

    const int tid  = threadIdx.x;
    const int row0 = blockIdx.x * BM;
    const int tx = tid & 15;
    const int ty = tid >> 4;

    if (tid < BNT) { s_sum[tid] = 0.f; s_sq[tid] = 0.f; }

    const int la_r = tid >> 2;
    const int la_k = (tid & 3) * 4;

    float acc[8][8];
#pragma unroll
    for (int i = 0; i < 8; i++)
#pragma unroll
        for (int j = 0; j < 8; j++) acc[i][j] = 0.f;

    for (int k0 = 0; k0 < H1; k0 += BK) {
        float4 sc = *(const float4*)(g_scale1 + k0 + la_k);
        float4 sh = *(const float4*)(g_shift1 + k0 + la_k);
#pragma unroll
        for (int h = 0; h < 2; h++) {
            int r = la_r + h * 64;
            float4 v = *(const float4*)(g_y + (size_t)(row0 + r) * H1 + k0 + la_k);
            As[la_k + 0][r] = fmaxf(fmaf(v.x, sc.x, sh.x), 0.f);
            As[la_k + 1][r] = fmaxf(fmaf(v.y, sc.y, sh.y), 0.f);
            As[la_k + 2][r] = fmaxf(fmaf(v.z, sc.z, sh.z), 0.f);
            As[la_k + 3][r] = fmaxf(fmaf(v.w, sc.w, sh.w), 0.f);
        }
#pragma unroll
        for (int h = 0; h < 2; h++) {
            int c = la_r + h * 64;
            float4 v = *(const float4*)(W2 + (size_t)c * H1 + k0 + la_k);
            Bs[la_k + 0][c] = v.x; Bs[la_k + 1][c] = v.y;
            Bs[la_k + 2][c] = v.z; Bs[la_k + 3][c] = v.w;
        }
        __syncthreads();
#pragma unroll
        for (int kk = 0; kk < BK; kk++) {
            float a[8], bv[8];
            *(float4*)&a[0]  = *(const float4*)&As[kk][ty * 8];
            *(float4*)&a[4]  = *(const float4*)&As[kk][ty * 8 + 4];
            *(float4*)&bv[0] = *(const float4*)&Bs[kk][tx * 8];
            *(float4*)&bv[4] = *(const float4*)&Bs[kk][tx * 8 + 4];
#pragma unroll
            for (int i = 0; i < 8; i++)
#pragma unroll
                for (int j = 0; j < 8; j++)
                    acc[i][j] = fmaf(a[i], bv[j], acc[i][j]);
        }
        __syncthreads();
    }

    float bias[8];
#pragma unroll
    for (int j = 0; j < 8; j++) bias[j] = b2[tx * 8 + j];

    float cs[8], cq[8];
#pragma unroll
    for (int j = 0; j < 8; j++) { cs[j] = 0.f; cq[j] = 0.f; }

#pragma unroll
    for (int i = 0; i < 8; i++) {
        const int r = row0 + ty * 8 + i;
        float* zr = out + (size_t)r * H2 + tx * 8;
        float v[8];
#pragma unroll
        for (int j = 0; j < 8; j++) {
            v[j] = acc[i][j] + bias[j];
            cs[j] += v[j];
            cq[j] += v[j] * v[j];
        }
        *(float4*)&zr[0] = make_float4(v[0], v[1], v[2], v[3]);
        *(float4*)&zr[4] = make_float4(v[4], v[5], v[6], v[7]);
    }
#pragma unroll
    for (int j = 0; j < 8; j++) {
        atomicAdd(&s_sum[tx * 8 + j], cs[j]);
        atomicAdd(&s_sq[tx * 8 + j], cq[j]);
    }
    __syncthreads();
    if (tid < BNT) {
        atomicAdd(&g_sum2[tid], s_sum[tid]);
        atomicAdd(&g_sumsq2[tid], s_sq[tid]);
    }
}

// ---------------- kernel 5: BN2 finalize ----------------
__global__ void bn2_finalize_kernel(const float* __restrict__ g2,
                                    const float* __restrict__ be2)
{
    int c = threadIdx.x;
    if (c < H2) {
        float mean = g_sum2[c] * (1.f / (float)M_TOTAL);
        float var  = g_sumsq2[c] * (1.f / (float)M_TOTAL) - mean * mean;
        float sc   = g2[c] / sqrtf(var + BN_EPS);
        g_scale2[c] = sc;
        g_shift2[c] = be2[c] - mean * sc;
    }
}

// ---------------- kernel 6: apply BN2 + ReLU in-place on d_out ----------------
__global__ __launch_bounds__(256) void final_bn_kernel(float* __restrict__ out) {
    const int i = blockIdx.x * blockDim.x + threadIdx.x;   // float4 index
    const int total4 = M_TOTAL * H2 / 4;
    if (i < total4) {
        float4 v = ((float4*)out)[i];
        int c = (i * 4) & (H2 - 1);
        v.x = fmaxf(fmaf(v.x, g_scale2[c + 0], g_shift2[c + 0]), 0.f);
        v.y = fmaxf(fmaf(v.y, g_scale2[c + 1], g_shift2[c + 1]), 0.f);
        v.z = fmaxf(fmaf(v.z, g_scale2[c + 2], g_shift2[c + 2]), 0.f);
        v.w = fmaxf(fmaf(v.w, g_scale2[c + 3], g_shift2[c + 3]), 0.f);
        ((float4*)out)[i] = v;
    }
}

// ---------------- launch ----------------
extern "C" void kernel_launch(void* const* d_in, const int* in_sizes, int n_in,
                              void* d_out, int out_size)
{
    const float* xyz1  = (const float*)d_in[0];
    const float* xyz2  = (const float*)d_in[1];
    const float* feat1 = (const float*)d_in[2];
    const float* feat2 = (const float*)d_in[3];
    const float* W1    = (const float*)d_in[4];
    const float* b1    = (const float*)d_in[5];
    const float* g1    = (const float*)d_in[6];
    const float* be1   = (const float*)d_in[7];
    const float* W2    = (const float*)d_in[8];
    const float* b2    = (const float*)d_in[9];
    const float* g2    = (const float*)d_in[10];
    const float* be2   = (const float*)d_in[11];
    float* out = (float*)d_out;

    zero_stats_kernel<<<1, 256>>>();

    dim3 gknn(NN / 256, BB);
    knn_interp_kernel<<<gknn, 256>>>(xyz1, xyz2, feat2);

    dim3 gg1(M_TOTAL / BM, H1 / BNT);
    gemm1_kernel<<<gg1, 256>>>(feat1, W1, b1);

    bn1_finalize_kernel<<<1, 256>>>(g1, be1);

    dim3 gg2(M_TOTAL / BM, 1);
    gemm2_kernel<<<gg2, 256>>>(W2, b2, out);

    bn2_finalize_kernel<<<1, 128>>>(g2, be2);

    final_bn_kernel<<<(M_TOTAL * H2 / 4 + 255) / 256, 256>>>(out);
}

// round 3
// speedup vs baseline: 1.8700x; 1.8700x over previous
#include <cuda_runtime.h>
#include <cuda_bf16.h>
#include <math.h>
#include <stdint.h>

#define BB 8
#define NN 8192
#define SS 2048
#define C1 128
#define C2 256
#define CIN 384
#define H1 256
#define H2 128
#define M_TOTAL (BB * NN)   /* 65536 */
#define BN_EPS 1e-5f

// ================= scratch (static device globals; no allocation) =================
__device__ float g_interp[(size_t)M_TOTAL * C2];   // 64 MB
__device__ float g_y[(size_t)M_TOTAL * H1];        // 64 MB
__device__ float g_sum1[H1];
__device__ float g_sumsq1[H1];
__device__ float g_sum2[H2];
__device__ float g_sumsq2[H2];
__device__ float g_scale1[H1];
__device__ float g_shift1[H1];
__device__ float g_scale2[H2];
__device__ float g_shift2[H2];
// weights as [n][k] bf16 hi/lo splits
__device__ __align__(16) __nv_bfloat16 g_W1hi[H1 * CIN];
__device__ __align__(16) __nv_bfloat16 g_W1lo[H1 * CIN];
__device__ __align__(16) __nv_bfloat16 g_W2hi[H2 * H1];
__device__ __align__(16) __nv_bfloat16 g_W2lo[H2 * H1];

// ================= helpers =================
__device__ __forceinline__ uint32_t smem_u32(const void* p) {
    uint32_t a;
    asm("{ .reg .u64 t; cvta.to.shared.u64 t, %1; cvt.u32.u64 %0, t; }" : "=r"(a) : "l"(p));
    return a;
}
__device__ __forceinline__ void ldsm4(uint32_t* r, uint32_t addr) {
    asm volatile("ldmatrix.sync.aligned.m8n8.x4.shared.b16 {%0,%1,%2,%3}, [%4];"
        : "=r"(r[0]), "=r"(r[1]), "=r"(r[2]), "=r"(r[3]) : "r"(addr));
}
__device__ __forceinline__ void ldsm2(uint32_t* r, uint32_t addr) {
    asm volatile("ldmatrix.sync.aligned.m8n8.x2.shared.b16 {%0,%1}, [%2];"
        : "=r"(r[0]), "=r"(r[1]) : "r"(addr));
}
__device__ __forceinline__ void mma_bf16(float* c, const uint32_t* a, const uint32_t* b) {
    asm volatile(
        "mma.sync.aligned.m16n8k16.row.col.f32.bf16.bf16.f32 "
        "{%0,%1,%2,%3}, {%4,%5,%6,%7}, {%8,%9}, {%0,%1,%2,%3};\n"
        : "+f"(c[0]), "+f"(c[1]), "+f"(c[2]), "+f"(c[3])
        : "r"(a[0]), "r"(a[1]), "r"(a[2]), "r"(a[3]), "r"(b[0]), "r"(b[1]));
}
__device__ __forceinline__ void cvt_hilo(float x, __nv_bfloat16& h, __nv_bfloat16& l) {
    h = __float2bfloat16_rn(x);
    l = __float2bfloat16_rn(x - __bfloat162float(h));
}

// ================= kernel: zero stats =================
__global__ void zero_stats_kernel() {
    int t = threadIdx.x;
    if (t < H1) { g_sum1[t] = 0.f; g_sumsq1[t] = 0.f; }
    if (t < H2) { g_sum2[t] = 0.f; g_sumsq2[t] = 0.f; }
}

// ================= kernel: weight prep (elementwise fp32 -> bf16 hi/lo) =================
__global__ void prep_weights_kernel(const float* __restrict__ W1, const float* __restrict__ W2) {
    int i = blockIdx.x * blockDim.x + threadIdx.x;
    if (i < H1 * CIN) {
        __nv_bfloat16 h, l;
        cvt_hilo(W1[i], h, l);
        g_W1hi[i] = h; g_W1lo[i] = l;
    }
    int j = i - H1 * CIN;
    if (j >= 0 && j < H2 * H1) {
        __nv_bfloat16 h, l;
        cvt_hilo(W2[j], h, l);
        g_W2hi[j] = h; g_W2lo[j] = l;
    }
}

// ================= kernel: 3-NN + interpolation =================
__global__ __launch_bounds__(256) void knn_interp_kernel(
    const float* __restrict__ xyz1,
    const float* __restrict__ xyz2,
    const float* __restrict__ feat2)
{
    __shared__ float4 s_p[SS];
    __shared__ float  s_w[256][3];
    __shared__ int    s_i[256][3];

    const int b   = blockIdx.y;
    const int n0  = blockIdx.x * 256;
    const int tid = threadIdx.x;

    const float* p2 = xyz2 + (size_t)b * SS * 3;
    for (int j = tid; j < SS; j += 256) {
        float x = p2[j * 3 + 0];
        float y = p2[j * 3 + 1];
        float z = p2[j * 3 + 2];
        s_p[j] = make_float4(x, y, z, x * x + y * y + z * z);
    }
    __syncthreads();

    const int   n   = n0 + tid;
    const float* q  = xyz1 + ((size_t)b * NN + n) * 3;
    const float qx = q[0], qy = q[1], qz = q[2];
    const float n1 = qx * qx + qy * qy + qz * qz;
    const float mx = -2.f * qx, my = -2.f * qy, mz = -2.f * qz;

    float d0 = 1e30f, d1 = 1e30f, d2v = 1e30f;
    int   i0 = 0, i1 = 0, i2 = 0;

#pragma unroll 8
    for (int j = 0; j < SS; j++) {
        float4 c = s_p[j];
        float s = fmaf(mx, c.x, fmaf(my, c.y, fmaf(mz, c.z, c.w)));
        if (s < d2v) {
            if (s < d1) {
                d2v = d1; i2 = i1;
                if (s < d0) { d1 = d0; i1 = i0; d0 = s; i0 = j; }
                else        { d1 = s;  i1 = j; }
            } else {
                d2v = s; i2 = j;
            }
        }
    }

    float da = sqrtf(fmaxf(n1 + d0, 0.f)) + 1e-10f;
    float db = sqrtf(fmaxf(n1 + d1, 0.f)) + 1e-10f;
    float dc = sqrtf(fmaxf(n1 + d2v, 0.f)) + 1e-10f;
    float w0 = 1.f / da, w1 = 1.f / db, w2 = 1.f / dc;
    float inv = 1.f / (w0 + w1 + w2);
    s_w[tid][0] = w0 * inv; s_w[tid][1] = w1 * inv; s_w[tid][2] = w2 * inv;
    s_i[tid][0] = i0; s_i[tid][1] = i1; s_i[tid][2] = i2;
    __syncthreads();

    const int lane = tid & 31;
    const int warp = tid >> 5;
    const float4* f2b = (const float4*)(feat2 + (size_t)b * SS * C2);
    for (int pl = warp; pl < 256; pl += 8) {
        const float a0 = s_w[pl][0], a1 = s_w[pl][1], a2 = s_w[pl][2];
        const float4* r0 = f2b + (size_t)s_i[pl][0] * (C2 / 4);
        const float4* r1 = f2b + (size_t)s_i[pl][1] * (C2 / 4);
        const float4* r2 = f2b + (size_t)s_i[pl][2] * (C2 / 4);
        float4* dst = (float4*)(g_interp + ((size_t)b * NN + n0 + pl) * C2);
#pragma unroll
        for (int c = lane; c < C2 / 4; c += 32) {
            float4 va = r0[c], vb = r1[c], vc = r2[c];
            float4 o;
            o.x = a0 * va.x + a1 * vb.x + a2 * vc.x;
            o.y = a0 * va.y + a1 * vb.y + a2 * vc.y;
            o.z = a0 * va.z + a1 * vb.z + a2 * vc.z;
            o.w = a0 * va.w + a1 * vb.w + a2 * vc.w;
            dst[c] = o;
        }
    }
}

// ================= warp-MMA GEMM (shared skeleton, templated) =================
// Block: 256 thr / 8 warps; tile 128(M) x 128(N) x 32(K); warp tile 64x32.
// SMEM per buffer (32KB): As_hi 8K | As_lo 8K | Bs_hi 8K | Bs_lo 8K; 2 buffers.
// Swizzle: 64B rows (32 bf16), 16B chunk c stored at c ^ ((row>>1)&3).

#define GEMM_SMEM_BUF 32768

template<int GEMM>   // 1: [interp|feat1] x W1 -> g_y ; 2: relu(bn1(g_y)) x W2 -> out
__global__ void __launch_bounds__(256, 1) gemm_mma_kernel(
    const float* __restrict__ A2,      // feat1 (GEMM1) / unused (GEMM2)
    const float* __restrict__ bias,    // b1 / b2
    float* __restrict__ dest_param)    // unused (GEMM1 -> g_y) / out (GEMM2)
{
    constexpr int KTOT = (GEMM == 1) ? CIN : H1;
    constexpr int NS   = KTOT / 32;
    constexpr int LDO  = (GEMM == 1) ? H1 : H2;

    extern __shared__ char smem[];
    const uint32_t sb = smem_u32(smem);
    const int tid  = threadIdx.x;
    const int lane = tid & 31;
    const int wid  = tid >> 5;
    const int wm   = wid & 1;          // 2 warps along M
    const int wn   = wid >> 1;         // 4 warps along N
    const int row0 = blockIdx.x * 128;
    const int col0 = blockIdx.y * 128;

    // GEMM2: stage BN1 scale/shift in smem (at 64KB offset)
    float* s_scale = (float*)(smem + 2 * GEMM_SMEM_BUF);
    float* s_shift = s_scale + H1;
    if (GEMM == 2) {
        if (tid < H1) { s_scale[tid] = g_scale1[tid]; s_shift[tid] = g_shift1[tid]; }
        __syncthreads();
    }

    // fragment ldmatrix address precompute
    int aoffB[4], asw[4];
#pragma unroll
    for (int mi = 0; mi < 4; mi++) {
        int r = wm * 64 + mi * 16 + (lane & 15);
        aoffB[mi] = r * 64;
        asw[mi]   = (r >> 1) & 3;
    }
    const int asel = lane >> 4;
    int boffB[4], bsw[4];
#pragma unroll
    for (int ni = 0; ni < 4; ni++) {
        int r = wn * 32 + ni * 8 + (lane & 7);
        boffB[ni] = r * 64;
        bsw[ni]   = (r >> 1) & 3;
    }
    const int bsel = (lane >> 3) & 1;

    float acc[4][4][4];
#pragma unroll
    for (int mi = 0; mi < 4; mi++)
#pragma unroll
        for (int ni = 0; ni < 4; ni++)
#pragma unroll
            for (int e = 0; e < 4; e++) acc[mi][ni][e] = 0.f;

    // per-thread stage-load assignment: row r (0..127), k-half kh (0/1) -> 16 elems
    const int r  = tid >> 1;
    const int kh = tid & 1;
    float4 av[4];
    uint4  bhr[2], blr[2];

    auto load_stage = [&](int s) {
        const int k0 = s * 32 + kh * 16;
        const __nv_bfloat16* wh = (GEMM == 1) ? g_W1hi : g_W2hi;
        const __nv_bfloat16* wl = (GEMM == 1) ? g_W1lo : g_W2lo;
        const __nv_bfloat16* ph = wh + (size_t)(col0 + r) * KTOT + k0;
        const __nv_bfloat16* pl = wl + (size_t)(col0 + r) * KTOT + k0;
        bhr[0] = *(const uint4*)ph;  bhr[1] = *(const uint4*)(ph + 8);
        blr[0] = *(const uint4*)pl;  blr[1] = *(const uint4*)(pl + 8);
        const float* pa;
        if (GEMM == 1) {
            if (k0 < C2) pa = g_interp + (size_t)(row0 + r) * C2 + k0;
            else         pa = A2       + (size_t)(row0 + r) * C1 + (k0 - C2);
        } else {
            pa = g_y + (size_t)(row0 + r) * H1 + k0;
        }
#pragma unroll
        for (int t = 0; t < 4; t++) av[t] = *(const float4*)(pa + 4 * t);
    };

    auto store_stage = [&](char* buf, int s) {
        float xs[16];
        *(float4*)&xs[0]  = av[0]; *(float4*)&xs[4]  = av[1];
        *(float4*)&xs[8]  = av[2]; *(float4*)&xs[12] = av[3];
        if (GEMM == 2) {
            const int k0 = s * 32 + kh * 16;
#pragma unroll
            for (int e = 0; e < 16; e++)
                xs[e] = fmaxf(fmaf(xs[e], s_scale[k0 + e], s_shift[k0 + e]), 0.f);
        }
        union U8 { uint4 u; __nv_bfloat16 b[8]; } h[2], l[2];
#pragma unroll
        for (int j = 0; j < 2; j++)
#pragma unroll
            for (int e = 0; e < 8; e++) cvt_hilo(xs[j * 8 + e], h[j].b[e], l[j].b[e]);
        const int sw = (r >> 1) & 3;
        const uint32_t base = r * 64;
        const int cb = kh * 2;
        uint32_t o0 = base + (((cb + 0) ^ sw) << 4);
        uint32_t o1 = base + (((cb + 1) ^ sw) << 4);
        *(uint4*)(buf +         o0) = h[0].u;
        *(uint4*)(buf +         o1) = h[1].u;
        *(uint4*)(buf +  8192 + o0) = l[0].u;
        *(uint4*)(buf +  8192 + o1) = l[1].u;
        *(uint4*)(buf + 16384 + o0) = bhr[0];
        *(uint4*)(buf + 16384 + o1) = bhr[1];
        *(uint4*)(buf + 24576 + o0) = blr[0];
        *(uint4*)(buf + 24576 + o1) = blr[1];
    };

    auto compute_stage = [&](uint32_t bufa) {
#pragma unroll
        for (int k16 = 0; k16 < 2; k16++) {
            uint32_t ah[4][4], al[4][4];
#pragma unroll
            for (int mi = 0; mi < 4; mi++) {
                uint32_t off = aoffB[mi] + ((((k16 * 2 + asel) ^ asw[mi])) << 4);
                ldsm4(ah[mi], bufa + off);
                ldsm4(al[mi], bufa + 8192 + off);
            }
            uint32_t bh[4][2], bl[4][2];
#pragma unroll
            for (int ni = 0; ni < 4; ni++) {
                uint32_t off = boffB[ni] + ((((k16 * 2 + bsel) ^ bsw[ni])) << 4);
                ldsm2(bh[ni], bufa + 16384 + off);
                ldsm2(bl[ni], bufa + 24576 + off);
            }
#pragma unroll
            for (int mi = 0; mi < 4; mi++)
#pragma unroll
                for (int ni = 0; ni < 4; ni++) {
                    mma_bf16(acc[mi][ni], ah[mi], bh[ni]);
                    mma_bf16(acc[mi][ni], ah[mi], bl[ni]);
                    mma_bf16(acc[mi][ni], al[mi], bh[ni]);
                }
        }
    };

    // pipeline
    load_stage(0);
    store_stage(smem, 0);
    __syncthreads();
#pragma unroll 1
    for (int s = 0; s < NS; s++) {
        if (s + 1 < NS) load_stage(s + 1);
        compute_stage(sb + (s & 1) * GEMM_SMEM_BUF);
        __syncthreads();
        if (s + 1 < NS) {
            store_stage(smem + ((s + 1) & 1) * GEMM_SMEM_BUF, s + 1);
            __syncthreads();
        }
    }

    // ---------------- epilogue: bias + store + channel stats ----------------
    float* dest = (GEMM == 1) ? g_y : dest_param;
    float* gsum = (GEMM == 1) ? g_sum1 : g_sum2;
    float* gsq  = (GEMM == 1) ? g_sumsq1 : g_sumsq2;
    const int g   = lane >> 2;
    const int tig = lane & 3;
#pragma unroll
    for (int ni = 0; ni < 4; ni++) {
        const int col = col0 + wn * 32 + ni * 8 + tig * 2;
        const float b0v = bias[col], b1v = bias[col + 1];
        float s0 = 0.f, s1 = 0.f, q0 = 0.f, q1 = 0.f;
#pragma unroll
        for (int mi = 0; mi < 4; mi++) {
            const int rA = row0 + wm * 64 + mi * 16 + g;
            float v00 = acc[mi][ni][0] + b0v, v01 = acc[mi][ni][1] + b1v;
            float v10 = acc[mi][ni][2] + b0v, v11 = acc[mi][ni][3] + b1v;
            *(float2*)(dest + (size_t)rA * LDO + col)       = make_float2(v00, v01);
            *(float2*)(dest + (size_t)(rA + 8) * LDO + col) = make_float2(v10, v11);
            s0 += v00 + v10; s1 += v01 + v11;
            q0 += v00 * v00 + v10 * v10; q1 += v01 * v01 + v11 * v11;
        }
#pragma unroll
        for (int m = 4; m <= 16; m <<= 1) {
            s0 += __shfl_xor_sync(0xffffffffu, s0, m);
            s1 += __shfl_xor_sync(0xffffffffu, s1, m);
            q0 += __shfl_xor_sync(0xffffffffu, q0, m);
            q1 += __shfl_xor_sync(0xffffffffu, q1, m);
        }
        if (lane < 4) {
            atomicAdd(&gsum[col], s0);
            atomicAdd(&gsum[col + 1], s1);
            atomicAdd(&gsq[col], q0);
            atomicAdd(&gsq[col + 1], q1);
        }
    }
}

// ================= BN finalize kernels =================
__global__ void bn1_finalize_kernel(const float* __restrict__ g1, const float* __restrict__ be1) {
    int c = threadIdx.x;
    if (c < H1) {
        float mean = g_sum1[c] * (1.f / (float)M_TOTAL);
        float var  = g_sumsq1[c] * (1.f / (float)M_TOTAL) - mean * mean;
        float sc   = g1[c] / sqrtf(var + BN_EPS);
        g_scale1[c] = sc;
        g_shift1[c] = be1[c] - mean * sc;
    }
}
__global__ void bn2_finalize_kernel(const float* __restrict__ g2, const float* __restrict__ be2) {
    int c = threadIdx.x;
    if (c < H2) {
        float mean = g_sum2[c] * (1.f / (float)M_TOTAL);
        float var  = g_sumsq2[c] * (1.f / (float)M_TOTAL) - mean * mean;
        float sc   = g2[c] / sqrtf(var + BN_EPS);
        g_scale2[c] = sc;
        g_shift2[c] = be2[c] - mean * sc;
    }
}

// ================= final BN2 + ReLU in-place =================
__global__ __launch_bounds__(256) void final_bn_kernel(float* __restrict__ out) {
    const int i = blockIdx.x * blockDim.x + threadIdx.x;
    const int total4 = M_TOTAL * H2 / 4;
    if (i < total4) {
        float4 v = ((float4*)out)[i];
        int c = (i * 4) & (H2 - 1);
        v.x = fmaxf(fmaf(v.x, g_scale2[c + 0], g_shift2[c + 0]), 0.f);
        v.y = fmaxf(fmaf(v.y, g_scale2[c + 1], g_shift2[c + 1]), 0.f);
        v.z = fmaxf(fmaf(v.z, g_scale2[c + 2], g_shift2[c + 2]), 0.f);
        v.w = fmaxf(fmaf(v.w, g_scale2[c + 3], g_shift2[c + 3]), 0.f);
        ((float4*)out)[i] = v;
    }
}

// ================= launch =================
extern "C" void kernel_launch(void* const* d_in, const int* in_sizes, int n_in,
                              void* d_out, int out_size)
{
    const float* xyz1  = (const float*)d_in[0];
    const float* xyz2  = (const float*)d_in[1];
    const float* feat1 = (const float*)d_in[2];
    const float* feat2 = (const float*)d_in[3];
    const float* W1    = (const float*)d_in[4];
    const float* b1    = (const float*)d_in[5];
    const float* g1    = (const float*)d_in[6];
    const float* be1   = (const float*)d_in[7];
    const float* W2    = (const float*)d_in[8];
    const float* b2    = (const float*)d_in[9];
    const float* g2    = (const float*)d_in[10];
    const float* be2   = (const float*)d_in[11];
    float* out = (float*)d_out;

    static bool attr_done = false;
    if (!attr_done) {
        cudaFuncSetAttribute(gemm_mma_kernel<1>, cudaFuncAttributeMaxDynamicSharedMemorySize,
                             2 * GEMM_SMEM_BUF);
        cudaFuncSetAttribute(gemm_mma_kernel<2>, cudaFuncAttributeMaxDynamicSharedMemorySize,
                             2 * GEMM_SMEM_BUF + 2048);
        attr_done = true;
    }

    zero_stats_kernel<<<1, 256>>>();
    prep_weights_kernel<<<(H1 * CIN + H2 * H1 + 255) / 256, 256>>>(W1, W2);

    dim3 gknn(NN / 256, BB);
    knn_interp_kernel<<<gknn, 256>>>(xyz1, xyz2, feat2);

    gemm_mma_kernel<1><<<dim3(M_TOTAL / 128, H1 / 128), 256, 2 * GEMM_SMEM_BUF>>>(feat1, b1, nullptr);

    bn1_finalize_kernel<<<1, 256>>>(g1, be1);

    gemm_mma_kernel<2><<<dim3(M_TOTAL / 128, 1), 256, 2 * GEMM_SMEM_BUF + 2048>>>(nullptr, b2, out);

    bn2_finalize_kernel<<<1, 128>>>(g2, be2);

    final_bn_kernel<<<(M_TOTAL * H2 / 4 + 255) / 256, 256>>>(out);
}